// round 7
// baseline (speedup 1.0000x reference)
#include <cuda_runtime.h>
#include <cstdint>

#define BATCH       64
#define SIZE        224
#define PIXELS      (SIZE*SIZE)        // 50176
#define DIM         40
#define NUM_CLASSES 10
#define TPX         128                // pixels per tile
#define TW          (TPX/32)           // 4 words per tile per dim
#define NTILE       (PIXELS/TPX)       // 392 blocks
#define MPITCH      5                  // sM pitch (odd -> conflict-free)

// One contiguous accumulator block, zeroed by zero_kernel each launch.
// Layout: [0, 2560)            g_A   : AND-popc per (b,d)
//         [2560, 2600)         g_Tot : popc(Q) per d
//         [2600, 2664)         g_C   : popc(M) per b
#define OFF_A   0
#define OFF_TOT (BATCH*DIM)
#define OFF_C   (BATCH*DIM + DIM)
#define ACC_N   (BATCH*DIM + DIM + BATCH)
__device__ int g_Acc[ACC_N];

// ---------------------------------------------------------------------------
__global__ void __launch_bounds__(1024)
zero_kernel() {
    const int tid = threadIdx.x;
    #pragma unroll
    for (int k = 0; k < 3; k++) {
        int i = k * 1024 + tid;
        if (i < ACC_N) g_Acc[i] = 0;
    }
}

// ---------------------------------------------------------------------------
// Fused kernel: block = one 128-pixel tile. Loads pos tile + x columns for all
// 64 batches once, ballots sign/mask bits, ANDs+popcounts in registers, and
// accumulates with integer global atomics (associative -> deterministic).
//
// Exactness: pos/level are exactly {-1,+1}; NUM_LEVELS=2 -> idx=round(x) with
// half-to-even so level-1 <=> x>0.5 strictly. All sums to `enc` are exact
// integers in both this kernel and the reference fp32 math.
// ---------------------------------------------------------------------------
__global__ void __launch_bounds__(256)
fused_kernel(const float* __restrict__ x,
             const float* __restrict__ pos) {
    const int tid  = threadIdx.x;
    const int lane = tid & 31;
    const int wid  = tid >> 5;                 // 8 warps
    const int p0   = blockIdx.x * TPX;

    __shared__ float    tile[TPX * 41];        // pos tile, pitch 41 (conflict-free cols)
    __shared__ uint32_t sM[BATCH * MPITCH];    // mask words, pitch 5 (conflict-free)

    // Phase 1: pos tile -> smem (coalesced; 20 elems/thread)
    #pragma unroll
    for (int k = 0; k < (TPX * DIM) / 256; k++) {
        int i = k * 256 + tid;
        int p = i / DIM, d = i - p * DIM;
        tile[p * 41 + d] = pos[(size_t)(p0 + p) * DIM + d];
    }

    // Phase 2 (independent of phase 1): mask-ballot x>0.5 for 8 batches/warp.
    // Coalesced 128B loads; results go to sM + popc accumulated per batch.
    #pragma unroll
    for (int k = 0; k < BATCH / 8; k++) {
        int b = wid + 8 * k;
        const float* __restrict__ xb = x + (size_t)b * PIXELS + p0;
        int cacc = 0;
        #pragma unroll
        for (int j = 0; j < TW; j++) {
            float v = xb[j * 32 + lane];
            unsigned m = __ballot_sync(0xffffffffu, v > 0.5f);
            cacc += __popc(m);
            if (lane == 0) sM[b * MPITCH + j] = m;
        }
        if (lane == 0) atomicAdd(&g_Acc[OFF_C + b], cacc);
    }
    __syncthreads();

    // Phase 3: Q-ballot per (d,j) and immediately AND against all 64 batch
    // masks. Per-lane accumulators: lane handles batches {lane, lane+32}.
    // Warp 'wid' covers dims wid, wid+8, ... (5 dims/warp, uniform).
    #pragma unroll
    for (int k = 0; k < DIM / 8; k++) {
        int d = wid + 8 * k;
        int a0 = 0, a1 = 0, tacc = 0;
        #pragma unroll
        for (int j = 0; j < TW; j++) {
            float v = tile[(j * 32 + lane) * 41 + d];   // stride 41: conflict-free
            unsigned q = __ballot_sync(0xffffffffu, v > 0.0f);
            tacc += __popc(q);
            a0 += __popc(q & sM[lane * MPITCH + j]);            // b = lane
            a1 += __popc(q & sM[(lane + 32) * MPITCH + j]);     // b = lane+32
        }
        atomicAdd(&g_Acc[OFF_A + lane * DIM + d], a0);
        atomicAdd(&g_Acc[OFF_A + (lane + 32) * DIM + d], a1);
        if (lane == 0) atomicAdd(&g_Acc[OFF_TOT + d], tacc);
    }
}

// ---------------------------------------------------------------------------
// Epilogue: 1 block. Exact integer epilogue -> sign -> classify.
// ---------------------------------------------------------------------------
__global__ void __launch_bounds__(1024)
epilogue_kernel(const float* __restrict__ lvl,   // [2, DIM]
                const float* __restrict__ cls,   // [10, DIM]
                float* __restrict__ out) {       // [BATCH, 10]
    __shared__ float enc[BATCH * DIM];
    const int tid = threadIdx.x;

    #pragma unroll
    for (int k = 0; k < 3; k++) {                 // covers 2560 with 1024 thr
        int p = k * 1024 + tid;
        if (p < BATCH * DIM) {
            int b = p / DIM, d = p - b * DIM;
            int A   = 2 * g_Acc[OFF_A + p]   - g_Acc[OFF_C + b];
            int Tot = 2 * g_Acc[OFF_TOT + d] - PIXELS;
            float summed = lvl[d] * (float)(Tot - A) + lvl[DIM + d] * (float)A;
            enc[p] = (summed > 0.0f) ? 1.0f : -1.0f;
        }
    }
    __syncthreads();

    if (tid < BATCH * NUM_CLASSES) {
        int b = tid / NUM_CLASSES, c = tid - b * NUM_CLASSES;
        float acc = 0.0f;
        #pragma unroll
        for (int d = 0; d < DIM; d++) acc += enc[b * DIM + d] * cls[c * DIM + d];
        out[tid] = acc;
    }
}

// ---------------------------------------------------------------------------
extern "C" void kernel_launch(void* const* d_in, const int* in_sizes, int n_in,
                              void* d_out, int out_size) {
    const float* x   = (const float*)d_in[0];   // [64, 224, 224]
    const float* pos = (const float*)d_in[1];   // [50176, 40]
    const float* lvl = (const float*)d_in[2];   // [2, 40]
    const float* cls = (const float*)d_in[3];   // [10, 40]
    float* out = (float*)d_out;                 // [64, 10]

    zero_kernel<<<1, 1024>>>();
    fused_kernel<<<NTILE, 256>>>(x, pos);
    epilogue_kernel<<<1, 1024>>>(lvl, cls, out);
}

// round 8
// speedup vs baseline: 1.9817x; 1.9817x over previous
#include <cuda_runtime.h>
#include <cstdint>

#define BATCH       64
#define SIZE        224
#define PIXELS      (SIZE*SIZE)        // 50176
#define DIM         40
#define NUM_CLASSES 10
#define WORDS       (PIXELS/32)        // 1568
#define NCHUNK      7                  // word chunks in main kernel
#define CW          (WORDS/NCHUNK)     // 224 words per chunk (exact)
#define QPITCH      225                // 224+1: conflict-free lane*QPITCH strides
#define PPB         64                 // pixels per pack block
#define NBP         (PIXELS/PPB)       // 784 pack blocks

// Packed pos sign bits per dim + deterministic partial accumulators
// (every slot written every launch -> no zeroing, no global atomics).
__device__ uint32_t g_Q[DIM * WORDS];              // 251 KB
__device__ int      g_TotPart[NCHUNK * DIM];       // popc(Q) per (chunk,d), from main b==0
__device__ int      g_Part[NCHUNK * BATCH * DIM];  // AND-popc per (chunk,b,d)
__device__ int      g_CPart[NCHUNK * BATCH];       // popc(M) per (chunk,b)

// ---------------------------------------------------------------------------
// Kernel A (pack v2): 784 blocks x 64 pixels. Coalesced load -> smem transpose
// (pitch 41) -> 80 ballots spread over 8 warps (10/warp). Pure pack.
// Exactness: pos/level are exactly {-1,+1}; NUM_LEVELS=2 -> idx=round(x) with
// half-to-even so level-1 <=> x>0.5 strictly. All sums to `enc` are exact
// integers in both this kernel and the reference fp32 math.
// ---------------------------------------------------------------------------
__global__ void __launch_bounds__(256)
pack_pos_kernel(const float* __restrict__ pos) {
    __shared__ float tile[PPB * 41];
    const int tid  = threadIdx.x;
    const int lane = tid & 31;
    const int wid  = tid >> 5;
    const int p0   = blockIdx.x * PPB;

    #pragma unroll
    for (int k = 0; k < (PPB * DIM) / 256; k++) {    // 10 coalesced loads/thread
        int i = k * 256 + tid;
        int p = i / DIM, d = i - p * DIM;
        tile[p * 41 + d] = pos[(size_t)(p0 + p) * DIM + d];
    }
    __syncthreads();

    #pragma unroll
    for (int k = 0; k < (DIM * 2) / 8; k++) {        // 40 dims x 2 words, 10/warp
        int t = wid + 8 * k;
        int d = t >> 1, j = t & 1;
        float v = tile[(j * 32 + lane) * 41 + d];    // stride 41: conflict-free
        unsigned q = __ballot_sync(0xffffffffu, v > 0.0f);
        if (lane == 0) g_Q[d * WORDS + (p0 >> 5) + j] = q;
    }
}

// ---------------------------------------------------------------------------
// Kernel B (unchanged from the measured-good R4 design, plus free Tot):
// block = (chunk c, batch b). Warp ballots x>0.5 on coalesced loads, ANDs with
// the shared Q chunk; per-lane dim accumulators. b==0 blocks also popc their
// sQ chunk -> g_TotPart (they already have it in shared).
// ---------------------------------------------------------------------------
__global__ void __launch_bounds__(256)
main_kernel(const float* __restrict__ x) {
    const int c = blockIdx.x >> 6;     // 0..6 (same-chunk blocks adjacent -> Q L2-hot)
    const int b = blockIdx.x & 63;
    const int tid  = threadIdx.x;
    const int lane = tid & 31;
    const int wid  = tid >> 5;

    __shared__ uint32_t sQ[DIM * QPITCH];
    __shared__ int sAcc[DIM];
    __shared__ int sCacc;

    if (tid < DIM) sAcc[tid] = 0;
    if (tid == 0)  sCacc = 0;

    const int w0 = c * CW;
    for (int i = tid; i < DIM * CW; i += 256) {
        int d = i / CW, j = i - d * CW;
        sQ[d * QPITCH + j] = g_Q[d * WORDS + w0 + j];   // L2-hot after first b
    }
    __syncthreads();

    // Warp 'wid' covers words [wid*28, wid*28+28) of this chunk.
    const float* __restrict__ xb = x + (size_t)b * PIXELS + (size_t)w0 * 32;
    const int jbase = wid * (CW / 8);                   // 28 words/warp
    int acc0 = 0, acc1 = 0, accC = 0;
    #pragma unroll 4
    for (int jj = 0; jj < CW / 8; jj++) {
        int j = jbase + jj;
        float v = xb[j * 32 + lane];                    // 128B coalesced
        unsigned m = __ballot_sync(0xffffffffu, v > 0.5f);
        accC += __popc(m);
        uint32_t q0 = sQ[lane * QPITCH + j];            // dim = lane
        acc0 += __popc(m & q0);
        if (lane < 8) {
            uint32_t q1 = sQ[(lane + 32) * QPITCH + j]; // dims 32..39
            acc1 += __popc(m & q1);
        }
    }
    atomicAdd(&sAcc[lane], acc0);
    if (lane < 8) atomicAdd(&sAcc[lane + 32], acc1);
    if (lane == 0) atomicAdd(&sCacc, accC);

    // Free Tot: the 7 b==0 blocks popc their resident sQ chunk.
    if (b == 0) {
        #pragma unroll
        for (int k = 0; k < DIM / 8; k++) {
            int d = wid + 8 * k;
            int t = 0;
            #pragma unroll
            for (int jj = 0; jj < CW / 32; jj++)        // 7 words/lane
                t += __popc(sQ[d * QPITCH + jj * 32 + lane]);
            t = __reduce_add_sync(0xffffffffu, t);
            if (lane == 0) g_TotPart[c * DIM + d] = t;
        }
    }
    __syncthreads();

    if (tid < DIM) g_Part[blockIdx.x * DIM + tid] = sAcc[tid];
    if (tid == 0)  g_CPart[blockIdx.x] = sCacc;
}

// ---------------------------------------------------------------------------
// Kernel C: single-block reduction + exact integer epilogue + classify.
// ---------------------------------------------------------------------------
__global__ void __launch_bounds__(1024)
epilogue_kernel(const float* __restrict__ lvl,   // [2, DIM]
                const float* __restrict__ cls,   // [10, DIM]
                float* __restrict__ out) {       // [BATCH, 10]
    __shared__ int   sTot[DIM];
    __shared__ int   sC[BATCH];
    __shared__ int   sA[BATCH * DIM];
    __shared__ float enc[BATCH * DIM];
    const int tid = threadIdx.x;

    if (tid < DIM) {
        int s = 0;
        #pragma unroll
        for (int c = 0; c < NCHUNK; c++) s += g_TotPart[c * DIM + tid];
        sTot[tid] = s;
    }
    for (int p = tid; p < BATCH * DIM; p += 1024) {      // 2560 (b,d) pairs
        int b = p / DIM, d = p - b * DIM;
        int s = 0;
        #pragma unroll
        for (int c = 0; c < NCHUNK; c++) s += g_Part[(c * BATCH + b) * DIM + d];
        sA[p] = s;
    }
    if (tid < BATCH) {
        int s = 0;
        #pragma unroll
        for (int c = 0; c < NCHUNK; c++) s += g_CPart[c * BATCH + tid];
        sC[tid] = s;
    }
    __syncthreads();

    for (int p = tid; p < BATCH * DIM; p += 1024) {
        int b = p / DIM, d = p - b * DIM;
        int A   = 2 * sA[p]   - sC[b];      // sum of pos over masked pixels
        int Tot = 2 * sTot[d] - PIXELS;     // sum of pos over all pixels
        float summed = lvl[d] * (float)(Tot - A) + lvl[DIM + d] * (float)A;
        enc[p] = (summed > 0.0f) ? 1.0f : -1.0f;
    }
    __syncthreads();

    if (tid < BATCH * NUM_CLASSES) {
        int b = tid / NUM_CLASSES, c = tid - b * NUM_CLASSES;
        float acc = 0.0f;
        #pragma unroll
        for (int d = 0; d < DIM; d++) acc += enc[b * DIM + d] * cls[c * DIM + d];
        out[tid] = acc;
    }
}

// ---------------------------------------------------------------------------
extern "C" void kernel_launch(void* const* d_in, const int* in_sizes, int n_in,
                              void* d_out, int out_size) {
    const float* x   = (const float*)d_in[0];   // [64, 224, 224]
    const float* pos = (const float*)d_in[1];   // [50176, 40]
    const float* lvl = (const float*)d_in[2];   // [2, 40]
    const float* cls = (const float*)d_in[3];   // [10, 40]
    float* out = (float*)d_out;                 // [64, 10]

    pack_pos_kernel<<<NBP, 256>>>(pos);
    main_kernel<<<NCHUNK * BATCH, 256>>>(x);
    epilogue_kernel<<<1, 1024>>>(lvl, cls, out);
}

// round 9
// speedup vs baseline: 2.7466x; 1.3860x over previous
#include <cuda_runtime.h>
#include <cstdint>

#define BATCH       64
#define SIZE        224
#define PIXELS      (SIZE*SIZE)        // 50176
#define DIM         40
#define NUM_CLASSES 10
#define WORDS       (PIXELS/32)        // 1568
#define NCHUNK      14                 // word chunks in main kernel
#define CW          (WORDS/NCHUNK)     // 112 words per chunk (exact)
#define QPITCH      113                // gcd(113,32)=1 -> conflict-free strides
#define PPB         64                 // pixels per pack block
#define NBP         (PIXELS/PPB)       // 784 pack blocks

// Packed pos sign bits per dim + deterministic partial accumulators
// (every slot written every launch -> no zeroing, no global atomics).
__device__ uint32_t g_Q[DIM * WORDS];              // 251 KB
__device__ int      g_TotPart[NCHUNK * DIM];       // popc(Q) per (chunk,d)
__device__ int      g_Part[NCHUNK * BATCH * DIM];  // AND-popc per (chunk,b,d)
__device__ int      g_CPart[NCHUNK * BATCH];       // popc(M) per (chunk,b)

// ---------------------------------------------------------------------------
// Kernel A (pack v3): 784 blocks x 64 pixels, 320 threads = 8 px x 40 dims.
// p,d computed once; loops use fixed increments (no div/mod in the hot path).
// Warp handles 4 dims: 2 ballots -> one STG.64.
// Exactness: pos/level are exactly {-1,+1}; NUM_LEVELS=2 -> idx=round(x) with
// half-to-even so level-1 <=> x>0.5 strictly. All sums to `enc` are exact
// integers in both this kernel and the reference fp32 math.
// ---------------------------------------------------------------------------
__global__ void __launch_bounds__(320)
pack_pos_kernel(const float* __restrict__ pos) {
    __shared__ float tile[PPB * 41];
    const int tid  = threadIdx.x;
    const int lane = tid & 31;
    const int wid  = tid >> 5;            // 10 warps
    const int p0   = blockIdx.x * PPB;

    // Phase 1: 8 iters x 320 threads = 2560 floats, fully coalesced.
    const int p = tid / DIM;              // once
    const int d = tid - p * DIM;          // once
    const float* __restrict__ src = pos + (size_t)(p0 + p) * DIM + d;
    float* dst = &tile[p * 41 + d];
    #pragma unroll
    for (int k = 0; k < PPB / 8; k++)
        dst[k * (8 * 41)] = src[k * (8 * DIM)];   // addr = fixed increments
    __syncthreads();

    // Phase 2: warp 'wid' packs dims [wid*4, wid*4+4), 2 words each, STG.64.
    #pragma unroll
    for (int k = 0; k < 4; k++) {
        int dd = wid * 4 + k;
        float v0 = tile[lane * 41 + dd];               // word 0, stride 41
        float v1 = tile[(32 + lane) * 41 + dd];        // word 1
        unsigned q0 = __ballot_sync(0xffffffffu, v0 > 0.0f);
        unsigned q1 = __ballot_sync(0xffffffffu, v1 > 0.0f);
        if (lane == 0) {
            uint2 w = make_uint2(q0, q1);
            *reinterpret_cast<uint2*>(&g_Q[dd * WORDS + (p0 >> 5)]) = w; // 8B-aligned
        }
    }
}

// ---------------------------------------------------------------------------
// Kernel B: block = (chunk c, batch-pair bp) -> 2 batches share the staged Q
// chunk (halves L2 staging traffic). uint4 staging loads. Per-lane dim
// accumulators; bp==0 blocks also emit Tot partials from resident sQ.
// ---------------------------------------------------------------------------
__global__ void __launch_bounds__(256)
main_kernel(const float* __restrict__ x) {
    const int c  = blockIdx.x >> 5;       // 0..13 (same-chunk blocks adjacent)
    const int bp = blockIdx.x & 31;
    const int b0 = bp * 2;
    const int tid  = threadIdx.x;
    const int lane = tid & 31;
    const int wid  = tid >> 5;            // 8 warps

    __shared__ uint32_t sQ[DIM * QPITCH];     // 17.7 KB
    __shared__ int sAcc0[DIM], sAcc1[DIM];
    __shared__ int sC0, sC1;

    if (tid < DIM) { sAcc0[tid] = 0; sAcc1[tid] = 0; }
    if (tid == 0)  { sC0 = 0; sC1 = 0; }

    const int w0 = c * CW;
    // Stage Q chunk: 40 dims x 28 uint4 = 1120 vec loads (16B-aligned).
    for (int i = tid; i < DIM * (CW / 4); i += 256) {
        int d = i / (CW / 4), j4 = i - d * (CW / 4);
        uint4 v = *reinterpret_cast<const uint4*>(&g_Q[d * WORDS + w0 + j4 * 4]);
        uint32_t* q = &sQ[d * QPITCH + j4 * 4];
        q[0] = v.x; q[1] = v.y; q[2] = v.z; q[3] = v.w;
    }
    __syncthreads();

    // Warp 'wid' covers words [wid*14, wid*14+14) of this chunk, 2 batches.
    const float* __restrict__ xb0 = x + (size_t)b0 * PIXELS + (size_t)w0 * 32;
    const float* __restrict__ xb1 = xb0 + PIXELS;
    const int jbase = wid * (CW / 8);                  // 14 words/warp
    int a00 = 0, a01 = 0, a10 = 0, a11 = 0, c0 = 0, c1 = 0;
    #pragma unroll
    for (int jj = 0; jj < CW / 8; jj++) {
        int j = jbase + jj;
        float v0 = xb0[j * 32 + lane];                 // 128B coalesced
        float v1 = xb1[j * 32 + lane];
        unsigned m0 = __ballot_sync(0xffffffffu, v0 > 0.5f);
        unsigned m1 = __ballot_sync(0xffffffffu, v1 > 0.5f);
        c0 += __popc(m0);
        c1 += __popc(m1);
        uint32_t q0 = sQ[lane * QPITCH + j];           // dim = lane
        a00 += __popc(m0 & q0);
        a10 += __popc(m1 & q0);
        if (lane < 8) {
            uint32_t q1 = sQ[(lane + 32) * QPITCH + j];// dims 32..39
            a01 += __popc(m0 & q1);
            a11 += __popc(m1 & q1);
        }
    }
    atomicAdd(&sAcc0[lane], a00);
    atomicAdd(&sAcc1[lane], a10);
    if (lane < 8) { atomicAdd(&sAcc0[lane + 32], a01); atomicAdd(&sAcc1[lane + 32], a11); }
    if (lane == 0) { atomicAdd(&sC0, c0); atomicAdd(&sC1, c1); }

    // Tot partials: the 14 bp==0 blocks popc their resident sQ chunk.
    if (bp == 0) {
        #pragma unroll
        for (int k = 0; k < DIM / 8; k++) {
            int d = wid + 8 * k;
            int t = 0;
            for (int j = lane; j < CW; j += 32)        // 3-4 words/lane
                t += __popc(sQ[d * QPITCH + j]);
            t = __reduce_add_sync(0xffffffffu, t);
            if (lane == 0) g_TotPart[c * DIM + d] = t;
        }
    }
    __syncthreads();

    if (tid < DIM) {
        g_Part[(c * BATCH + b0) * DIM + tid]     = sAcc0[tid];
        g_Part[(c * BATCH + b0 + 1) * DIM + tid] = sAcc1[tid];
    }
    if (tid == 0) {
        g_CPart[c * BATCH + b0]     = sC0;
        g_CPart[c * BATCH + b0 + 1] = sC1;
    }
}

// ---------------------------------------------------------------------------
// Kernel C: 64 blocks (one per batch) -> no single-block latency floor.
// Chunk-sum + exact integer epilogue + sign + classify.
// ---------------------------------------------------------------------------
__global__ void __launch_bounds__(64)
epilogue_kernel(const float* __restrict__ lvl,   // [2, DIM]
                const float* __restrict__ cls,   // [10, DIM]
                float* __restrict__ out) {       // [BATCH, 10]
    const int b   = blockIdx.x;
    const int tid = threadIdx.x;
    __shared__ float enc[DIM];
    __shared__ int   sC;

    if (tid == 0) {
        int s = 0;
        #pragma unroll
        for (int c = 0; c < NCHUNK; c++) s += g_CPart[c * BATCH + b];
        sC = s;
    }
    __syncthreads();

    if (tid < DIM) {
        int sA = 0, sT = 0;
        #pragma unroll
        for (int c = 0; c < NCHUNK; c++) {
            sA += g_Part[(c * BATCH + b) * DIM + tid];
            sT += g_TotPart[c * DIM + tid];
        }
        int A   = 2 * sA - sC;              // sum of pos over masked pixels
        int Tot = 2 * sT - PIXELS;          // sum of pos over all pixels
        float summed = lvl[tid] * (float)(Tot - A) + lvl[DIM + tid] * (float)A;
        enc[tid] = (summed > 0.0f) ? 1.0f : -1.0f;
    }
    __syncthreads();

    if (tid < NUM_CLASSES) {
        float acc = 0.0f;
        #pragma unroll
        for (int d = 0; d < DIM; d++) acc += enc[d] * cls[tid * DIM + d];
        out[b * NUM_CLASSES + tid] = acc;
    }
}

// ---------------------------------------------------------------------------
extern "C" void kernel_launch(void* const* d_in, const int* in_sizes, int n_in,
                              void* d_out, int out_size) {
    const float* x   = (const float*)d_in[0];   // [64, 224, 224]
    const float* pos = (const float*)d_in[1];   // [50176, 40]
    const float* lvl = (const float*)d_in[2];   // [2, 40]
    const float* cls = (const float*)d_in[3];   // [10, 40]
    float* out = (float*)d_out;                 // [64, 10]

    pack_pos_kernel<<<NBP, 320>>>(pos);
    main_kernel<<<NCHUNK * 32, 256>>>(x);
    epilogue_kernel<<<BATCH, 64>>>(lvl, cls, out);
}